// round 12
// baseline (speedup 1.0000x reference)
#include <cuda_runtime.h>
#include <math.h>
#include <stdint.h>
#include <cstdint>

#define NBULK        62
#define DDIM         64
#define NBATCH       8192
#define PSI_BLOCKS   128
#define TOTAL_BLOCKS (1 + PSI_BLOCKS)
#define NTHREADS     512
#define MBLK         64

// ---------------- psi-block shared memory layout (float offsets) -------------
#define ENV_STRIDE 68
#define SM_ENV     0                        // 64*68 = 4352 (env[m][k])
#define SM_RIGHT   4352                     // 128
#define SM_RED     4480                     // 256 ([4 ng][64 m])
#define SM_CFG     4736                     // 1024 floats = 4096 B (cfgS[site][m])
#define SM_B       5760                     // byte 23040 (128B aligned); 2 x 16384
#define PSI_TOTALF (5760 + 2 * 16384)

// ---------------- logz-block shared memory layout ----------------------------
#define LZ_ENV   0                          // 64*68 = 4352 (env[i][j])
#define LZ_TMP   4352                       // 64*132 = 8448 (tmp[d][(p,j)])
#define LZ_B1    12800                      // 16384 (phase1 B hi|lo, frag order)
#define LZ_B2    29184                      // 16384 (phase2 B hi|lo, frag order)
#define LZ_RED   45568                      // 256 (maxw + z reduce)
#define LZ_TOTALF 45824

#define SM_TOTALF LZ_TOTALF                 // 183296 bytes

// ---------------- global scratch (zero-initialized at load) ------------------
__device__ float    g_bulkT [(size_t)NBULK * 16384];  // psi/logz-ph1 B frags hi|lo
__device__ float    g_bulkT2[(size_t)NBULK * 16384];  // logz-ph2 B frags hi|lo
__device__ float    g_blocksums[PSI_BLOCKS];
__device__ float    g_logz;
__device__ unsigned g_fin;

__device__ __forceinline__ void cp16(unsigned dst, const void* src) {
    asm volatile("cp.async.cg.shared.global [%0], [%1], 16;" :: "r"(dst), "l"(src) : "memory");
}
__device__ __forceinline__ void cp_commit() { asm volatile("cp.async.commit_group;" ::: "memory"); }
__device__ __forceinline__ void cp_wait0()  { asm volatile("cp.async.wait_group 0;" ::: "memory"); }

// m16n8k8 tf32 MMA, f32 accumulate in-place
__device__ __forceinline__ void mma8(float* d,
                                     unsigned a0, unsigned a1, unsigned a2, unsigned a3,
                                     unsigned b0, unsigned b1) {
    asm volatile("mma.sync.aligned.m16n8k8.row.col.f32.tf32.tf32.f32 "
                 "{%0,%1,%2,%3}, {%4,%5,%6,%7}, {%8,%9}, {%0,%1,%2,%3};"
                 : "+f"(d[0]), "+f"(d[1]), "+f"(d[2]), "+f"(d[3])
                 : "r"(a0), "r"(a1), "r"(a2), "r"(a3), "r"(b0), "r"(b1));
}

// ============ pre-pass: bake tf32 hi/lo fragment-order operands ==============
__global__ void pre_kernel(const float* __restrict__ bulk) {
    const int t = blockIdx.x;
    const float* src = bulk + (size_t)t * 8192;       // [d][n], n = p*64+j
    float* d1 = g_bulkT  + (size_t)t * 16384;
    float* d2 = g_bulkT2 + (size_t)t * 16384;
    for (int idx = threadIdx.x; idx < 8192; idx += blockDim.x) {
        int k = idx >> 7, n = idx & 127;
        float v = src[idx];
        unsigned hb = __float_as_uint(v) & 0xFFFFE000u;
        float lof = v - __uint_as_float(hb);
        unsigned lb = __float_as_uint(lof) & 0xFFFFE000u;
        int kt   = k >> 3;
        int lane = ((n & 7) << 2) | (k & 3);
        int b    = (k >> 2) & 1;
        int ntp  = n >> 4;
        int q    = (((n >> 3) & 1) << 1) | b;
        int off  = kt * 1024 + ntp * 128 + lane * 4 + q;
        d1[off]        = __uint_as_float(hb);
        d1[8192 + off] = __uint_as_float(lb);
    }
    for (int idx = threadIdx.x; idx < 8192; idx += blockDim.x) {
        int K = idx >> 6, n = idx & 63;
        float v = src[(K & 63) * 128 + (K >> 6) * 64 + n];
        unsigned hb = __float_as_uint(v) & 0xFFFFE000u;
        float lof = v - __uint_as_float(hb);
        unsigned lb = __float_as_uint(lof) & 0xFFFFE000u;
        int kt   = K >> 3;
        int lane = ((n & 7) << 2) | (K & 3);
        int b    = (K >> 2) & 1;
        int ntp  = n >> 4;
        int q    = (((n >> 3) & 1) << 1) | b;
        int off  = kt * 512 + ntp * 128 + lane * 4 + q;
        d2[off]        = __uint_as_float(hb);
        d2[8192 + off] = __uint_as_float(lb);
    }
}

__global__ __launch_bounds__(NTHREADS, 1)
void main_kernel(const int* __restrict__ cfg,
                 const float* __restrict__ left,
                 const float* __restrict__ bulk,
                 const float* __restrict__ right,
                 float* __restrict__ out) {
    extern __shared__ float smem[];
    const int tid = threadIdx.x;
    const int lane = tid & 31;
    const int w = tid >> 5;
    const int g = lane >> 2, tq = lane & 3;
    const unsigned smem_base = (unsigned)__cvta_generic_to_shared(smem);

    if (blockIdx.x == 0) {
        // ========== log-Z: ONE block, tensor cores, split-K chains ==========
        unsigned* maxw = (unsigned*)(smem + LZ_RED);
        const unsigned b1_addr = smem_base + LZ_B1 * 4;
        const unsigned b2_addr = smem_base + LZ_B2 * 4;

        for (int idx = tid; idx < 4096; idx += NTHREADS) {
            int i = idx >> 6, j = idx & 63;
            smem[LZ_ENV + i * ENV_STRIDE + j] =
                left[i] * left[j] + left[64 + i] * left[64 + j];
        }
        {
            const float4* s1 = (const float4*)g_bulkT;
            const float4* s2 = (const float4*)g_bulkT2;
#pragma unroll
            for (int i = 0; i < 8; i++)
                cp16(b1_addr + (unsigned)(tid + (i << 9)) * 16u, s1 + tid + (i << 9));
#pragma unroll
            for (int i = 0; i < 8; i++)
                cp16(b2_addr + (unsigned)(tid + (i << 9)) * 16u, s2 + tid + (i << 9));
            cp_commit();
        }

        const int mt = w & 3;
        const int ng = w >> 2;          // 0..3
        const int r0 = mt * 16 + g, r1 = r0 + 8;
        float log_scale = 0.0f;

        for (int t = 0; t < NBULK; t++) {
            cp_wait0();
            __syncthreads();

            // ---- phase1: tmp = env @ [A0|A1], 3xTF32, split-K banks ----
            {
                float dh[2][4][4], dl1[2][4][4], dl2[4][4];
#pragma unroll
                for (int i = 0; i < 4; i++)
#pragma unroll
                    for (int j = 0; j < 4; j++) {
                        dh[0][i][j] = 0.f; dh[1][i][j] = 0.f;
                        dl1[0][i][j] = 0.f; dl1[1][i][j] = 0.f;
                        dl2[i][j] = 0.f;
                    }
                const float4* Bh4 = (const float4*)(smem + LZ_B1);
                const float4* Bl4 = Bh4 + 2048;
#pragma unroll
                for (int kt = 0; kt < 8; kt++) {
                    const int ks = kt >> 2;
                    const int c0 = kt * 8 + tq;
                    float v0 = smem[LZ_ENV + r0 * ENV_STRIDE + c0];
                    float v1 = smem[LZ_ENV + r1 * ENV_STRIDE + c0];
                    float v2 = smem[LZ_ENV + r0 * ENV_STRIDE + c0 + 4];
                    float v3 = smem[LZ_ENV + r1 * ENV_STRIDE + c0 + 4];
                    unsigned h0 = __float_as_uint(v0) & 0xFFFFE000u;
                    unsigned h1 = __float_as_uint(v1) & 0xFFFFE000u;
                    unsigned h2 = __float_as_uint(v2) & 0xFFFFE000u;
                    unsigned h3 = __float_as_uint(v3) & 0xFFFFE000u;
                    unsigned l0 = __float_as_uint(v0 - __uint_as_float(h0)) & 0xFFFFE000u;
                    unsigned l1 = __float_as_uint(v1 - __uint_as_float(h1)) & 0xFFFFE000u;
                    unsigned l2 = __float_as_uint(v2 - __uint_as_float(h2)) & 0xFFFFE000u;
                    unsigned l3 = __float_as_uint(v3 - __uint_as_float(h3)) & 0xFFFFE000u;
                    float4 bh0 = Bh4[kt * 256 + (ng * 2 + 0) * 32 + lane];
                    float4 bh1 = Bh4[kt * 256 + (ng * 2 + 1) * 32 + lane];
                    float4 bl0 = Bl4[kt * 256 + (ng * 2 + 0) * 32 + lane];
                    float4 bl1 = Bl4[kt * 256 + (ng * 2 + 1) * 32 + lane];
#pragma unroll
                    for (int ntl = 0; ntl < 4; ntl++) {
                        const float4& bh = (ntl >> 1) ? bh1 : bh0;
                        const float4& bl = (ntl >> 1) ? bl1 : bl0;
                        unsigned b0 = __float_as_uint((ntl & 1) ? bh.z : bh.x);
                        unsigned b1 = __float_as_uint((ntl & 1) ? bh.w : bh.y);
                        unsigned c0b = __float_as_uint((ntl & 1) ? bl.z : bl.x);
                        unsigned c1b = __float_as_uint((ntl & 1) ? bl.w : bl.y);
                        mma8(dh[ks][ntl],  h0, h1, h2, h3, b0, b1);
                        mma8(dl1[ks][ntl], l0, l1, l2, l3, b0, b1);
                        mma8(dl2[ntl],     h0, h1, h2, h3, c0b, c1b);
                    }
                }
#pragma unroll
                for (int ntl = 0; ntl < 4; ntl++) {
                    const int j0 = (ng * 4 + ntl) * 8 + 2 * tq;
                    float s0 = dh[0][ntl][0] + dh[1][ntl][0] + dl1[0][ntl][0] + dl1[1][ntl][0] + dl2[ntl][0];
                    float s1 = dh[0][ntl][1] + dh[1][ntl][1] + dl1[0][ntl][1] + dl1[1][ntl][1] + dl2[ntl][1];
                    float s2 = dh[0][ntl][2] + dh[1][ntl][2] + dl1[0][ntl][2] + dl1[1][ntl][2] + dl2[ntl][2];
                    float s3 = dh[0][ntl][3] + dh[1][ntl][3] + dl1[0][ntl][3] + dl1[1][ntl][3] + dl2[ntl][3];
                    *(float2*)&smem[LZ_TMP + r0 * 132 + j0] = make_float2(s0, s1);
                    *(float2*)&smem[LZ_TMP + r1 * 132 + j0] = make_float2(s2, s3);
                }
            }
            if (tid == 0) *maxw = 0u;
            __syncthreads();

            if (t + 1 < NBULK) {
                const float4* s1 = (const float4*)(g_bulkT + (size_t)(t + 1) * 16384);
#pragma unroll
                for (int i = 0; i < 8; i++)
                    cp16(b1_addr + (unsigned)(tid + (i << 9)) * 16u, s1 + tid + (i << 9));
                cp_commit();
            }

            // ---- phase2: env' = tmp-GEMM, split-K (2 halves of 16 steps) ----
            float ds[2][4];
            {
                float dh[2][2][4], dl1[2][2][4], dl2[2][2][4];
#pragma unroll
                for (int i = 0; i < 2; i++)
#pragma unroll
                    for (int j = 0; j < 4; j++) {
                        dh[0][i][j] = 0.f; dh[1][i][j] = 0.f;
                        dl1[0][i][j] = 0.f; dl1[1][i][j] = 0.f;
                        dl2[0][i][j] = 0.f; dl2[1][i][j] = 0.f;
                    }
                const float4* B2h4 = (const float4*)(smem + LZ_B2);
                const float4* B2l4 = B2h4 + 2048;
#pragma unroll
                for (int kt2 = 0; kt2 < 16; kt2++) {
                    const int ks = kt2 >> 3;
                    const int K0 = kt2 * 8 + tq;
                    const int a0off = (K0 & 63) * 132 + (K0 >> 6) * 64;
                    const int a1off = ((K0 + 4) & 63) * 132 + ((K0 + 4) >> 6) * 64;
                    float v0 = smem[LZ_TMP + a0off + r0];
                    float v1 = smem[LZ_TMP + a0off + r1];
                    float v2 = smem[LZ_TMP + a1off + r0];
                    float v3 = smem[LZ_TMP + a1off + r1];
                    unsigned h0 = __float_as_uint(v0) & 0xFFFFE000u;
                    unsigned h1 = __float_as_uint(v1) & 0xFFFFE000u;
                    unsigned h2 = __float_as_uint(v2) & 0xFFFFE000u;
                    unsigned h3 = __float_as_uint(v3) & 0xFFFFE000u;
                    unsigned l0 = __float_as_uint(v0 - __uint_as_float(h0)) & 0xFFFFE000u;
                    unsigned l1 = __float_as_uint(v1 - __uint_as_float(h1)) & 0xFFFFE000u;
                    unsigned l2 = __float_as_uint(v2 - __uint_as_float(h2)) & 0xFFFFE000u;
                    unsigned l3 = __float_as_uint(v3 - __uint_as_float(h3)) & 0xFFFFE000u;
                    float4 bh = B2h4[kt2 * 128 + ng * 32 + lane];
                    float4 bl = B2l4[kt2 * 128 + ng * 32 + lane];
#pragma unroll
                    for (int ntl = 0; ntl < 2; ntl++) {
                        unsigned b0 = __float_as_uint(ntl ? bh.z : bh.x);
                        unsigned b1 = __float_as_uint(ntl ? bh.w : bh.y);
                        unsigned c0b = __float_as_uint(ntl ? bl.z : bl.x);
                        unsigned c1b = __float_as_uint(ntl ? bl.w : bl.y);
                        mma8(dh[ks][ntl],  h0, h1, h2, h3, b0, b1);
                        mma8(dl1[ks][ntl], l0, l1, l2, l3, b0, b1);
                        mma8(dl2[ks][ntl], h0, h1, h2, h3, c0b, c1b);
                    }
                }
                float am = 0.0f;
#pragma unroll
                for (int ntl = 0; ntl < 2; ntl++)
#pragma unroll
                    for (int j = 0; j < 4; j++) {
                        ds[ntl][j] = dh[0][ntl][j] + dh[1][ntl][j]
                                   + dl1[0][ntl][j] + dl1[1][ntl][j]
                                   + dl2[0][ntl][j] + dl2[1][ntl][j];
                        am = fmaxf(am, fabsf(ds[ntl][j]));
                    }
#pragma unroll
                for (int off = 16; off > 0; off >>= 1)
                    am = fmaxf(am, __shfl_xor_sync(0xffffffffu, am, off));
                if (lane == 0) atomicMax(maxw, __float_as_uint(am));
            }
            __syncthreads();

            if (t + 1 < NBULK) {
                const float4* s2 = (const float4*)(g_bulkT2 + (size_t)(t + 1) * 16384);
#pragma unroll
                for (int i = 0; i < 8; i++)
                    cp16(b2_addr + (unsigned)(tid + (i << 9)) * 16u, s2 + tid + (i << 9));
                cp_commit();
            }

            const float scale = fmaxf(__uint_as_float(*maxw), 1e-30f);
            log_scale += logf(scale);
            const float inv = 1.0f / scale;
#pragma unroll
            for (int ntl = 0; ntl < 2; ntl++) {
                const int i0 = (ng * 2 + ntl) * 8 + 2 * tq;
                *(float2*)&smem[LZ_ENV + r0 * ENV_STRIDE + i0] =
                    make_float2(ds[ntl][0] * inv, ds[ntl][1] * inv);
                *(float2*)&smem[LZ_ENV + r1 * ENV_STRIDE + i0] =
                    make_float2(ds[ntl][2] * inv, ds[ntl][3] * inv);
            }
        }
        __syncthreads();

        float part = 0.0f;
        if (tid < 128) {
            int k = tid & 63, pp = tid >> 6;
            float s = 0.0f;
#pragma unroll 8
            for (int e = 0; e < 64; e++)
                s = fmaf(smem[LZ_ENV + k * ENV_STRIDE + e], right[e * 2 + pp], s);
            part = right[k * 2 + pp] * s;
        }
        if (tid < 128) smem[LZ_RED + 32 + tid] = part;
        __syncthreads();
        if (tid == 0) {
            float z = 0.0f;
            for (int i = 0; i < 128; i++) z += smem[LZ_RED + 32 + i];
            g_logz = logf(fmaxf(z, 1e-30f)) + log_scale;
            __threadfence();
            unsigned o = atomicAdd(&g_fin, 1u);
            if (o == PSI_BLOCKS) {
                float s = 0.0f;
                for (int i = 0; i < PSI_BLOCKS; i++) s += __ldcg(&g_blocksums[i]);
                out[0] = g_logz - s * (1.0f / (float)NBATCH);
                __threadfence();
                g_fin = 0;
                __threadfence();
            }
        }
        return;
    }

    // ======= psi: 128 blocks x 64 samples, split-K mma.sync tf32 ==============
    const int bi = blockIdx.x - 1;
    const int m0 = bi * MBLK;
    const int mt = w & 3;
    const int ng = w >> 2;
    const int h = ng >> 1;
    const int r0 = mt * 16 + g, r1 = r0 + 8;
    unsigned char* cfgS = (unsigned char*)(smem + SM_CFG);
    const unsigned smemB_base = smem_base + SM_B * 4;

    {
        const float4* src = (const float4*)g_bulkT;
#pragma unroll
        for (int i = 0; i < 8; i++)
            cp16(smemB_base + (unsigned)(tid + (i << 9)) * 16u, src + tid + (i << 9));
        cp_commit();
    }

    for (int idx = tid; idx < 64 * MBLK; idx += NTHREADS) {
        int mm = idx >> 6, s = idx & 63;
        cfgS[s * MBLK + mm] = (unsigned char)cfg[(size_t)(m0 + mm) * 64 + s];
    }
    if (tid < 128) smem[SM_RIGHT + tid] = right[tid];
    __syncthreads();

    for (int idx = tid; idx < 64 * 64; idx += NTHREADS) {
        int k = idx >> 6, mm = idx & 63;
        smem[SM_ENV + mm * ENV_STRIDE + k] = left[(int)cfgS[mm] * 64 + k];
    }

    float ps0 = 0.0f, ps1 = 0.0f;

    for (int t = 0; t < NBULK; t++) {
        cp_wait0();
        __syncthreads();

        if (t + 1 < NBULK) {
            const float4* src = (const float4*)(g_bulkT + (size_t)(t + 1) * 16384);
            unsigned dst = smemB_base + (unsigned)(((t + 1) & 1) * 65536u);
#pragma unroll
            for (int i = 0; i < 8; i++)
                cp16(dst + (unsigned)(tid + (i << 9)) * 16u, src + tid + (i << 9));
            cp_commit();
        }

        const float4* Bh4 = (const float4*)(smem + SM_B + (t & 1) * 16384);
        const float4* Bl4 = Bh4 + 2048;

        float dh[2][4][4], dl1[2][4][4], dl2[4][4];
#pragma unroll
        for (int i = 0; i < 4; i++)
#pragma unroll
            for (int j = 0; j < 4; j++) {
                dh[0][i][j] = 0.f; dh[1][i][j] = 0.f;
                dl1[0][i][j] = 0.f; dl1[1][i][j] = 0.f;
                dl2[i][j] = 0.f;
            }

#pragma unroll
        for (int kt = 0; kt < 8; kt++) {
            const int ks = kt >> 2;
            const int c0 = kt * 8 + tq;
            float v0 = smem[SM_ENV + r0 * ENV_STRIDE + c0];
            float v1 = smem[SM_ENV + r1 * ENV_STRIDE + c0];
            float v2 = smem[SM_ENV + r0 * ENV_STRIDE + c0 + 4];
            float v3 = smem[SM_ENV + r1 * ENV_STRIDE + c0 + 4];
            unsigned h0 = __float_as_uint(v0) & 0xFFFFE000u;
            unsigned h1 = __float_as_uint(v1) & 0xFFFFE000u;
            unsigned h2 = __float_as_uint(v2) & 0xFFFFE000u;
            unsigned h3 = __float_as_uint(v3) & 0xFFFFE000u;
            unsigned l0 = __float_as_uint(v0 - __uint_as_float(h0)) & 0xFFFFE000u;
            unsigned l1 = __float_as_uint(v1 - __uint_as_float(h1)) & 0xFFFFE000u;
            unsigned l2 = __float_as_uint(v2 - __uint_as_float(h2)) & 0xFFFFE000u;
            unsigned l3 = __float_as_uint(v3 - __uint_as_float(h3)) & 0xFFFFE000u;
            float4 bh0 = Bh4[kt * 256 + (ng * 2 + 0) * 32 + lane];
            float4 bh1 = Bh4[kt * 256 + (ng * 2 + 1) * 32 + lane];
            float4 bl0 = Bl4[kt * 256 + (ng * 2 + 0) * 32 + lane];
            float4 bl1 = Bl4[kt * 256 + (ng * 2 + 1) * 32 + lane];
#pragma unroll
            for (int ntl = 0; ntl < 4; ntl++) {
                const float4& bh = (ntl >> 1) ? bh1 : bh0;
                const float4& bl = (ntl >> 1) ? bl1 : bl0;
                unsigned b0 = __float_as_uint((ntl & 1) ? bh.z : bh.x);
                unsigned b1 = __float_as_uint((ntl & 1) ? bh.w : bh.y);
                unsigned c0b = __float_as_uint((ntl & 1) ? bl.z : bl.x);
                unsigned c1b = __float_as_uint((ntl & 1) ? bl.w : bl.y);
                mma8(dh[ks][ntl],  h0, h1, h2, h3, b0, b1);
                mma8(dl1[ks][ntl], l0, l1, l2, l3, b0, b1);
                mma8(dl2[ntl],     h0, h1, h2, h3, c0b, c1b);
            }
        }
        __syncthreads();

        if (t < NBULK - 1) {
            const int sel0 = cfgS[(t + 1) * MBLK + r0];
            const int sel1 = cfgS[(t + 1) * MBLK + r1];
#pragma unroll
            for (int ntl = 0; ntl < 4; ntl++) {
                const int j0 = (ng & 1) * 32 + ntl * 8 + 2 * tq;
                if (sel0 == h)
                    *(float2*)&smem[SM_ENV + r0 * ENV_STRIDE + j0] =
                        make_float2(dh[0][ntl][0] + dh[1][ntl][0] + dl1[0][ntl][0] + dl1[1][ntl][0] + dl2[ntl][0],
                                    dh[0][ntl][1] + dh[1][ntl][1] + dl1[0][ntl][1] + dl1[1][ntl][1] + dl2[ntl][1]);
                if (sel1 == h)
                    *(float2*)&smem[SM_ENV + r1 * ENV_STRIDE + j0] =
                        make_float2(dh[0][ntl][2] + dh[1][ntl][2] + dl1[0][ntl][2] + dl1[1][ntl][2] + dl2[ntl][2],
                                    dh[0][ntl][3] + dh[1][ntl][3] + dl1[0][ntl][3] + dl1[1][ntl][3] + dl2[ntl][3]);
            }
        } else {
            const int sel0 = cfgS[62 * MBLK + r0], sl0 = cfgS[63 * MBLK + r0];
            const int sel1 = cfgS[62 * MBLK + r1], sl1 = cfgS[63 * MBLK + r1];
#pragma unroll
            for (int ntl = 0; ntl < 4; ntl++) {
                const int j0 = (ng & 1) * 32 + ntl * 8 + 2 * tq;
                if (sel0 == h) {
                    float a = dh[0][ntl][0] + dh[1][ntl][0] + dl1[0][ntl][0] + dl1[1][ntl][0] + dl2[ntl][0];
                    float b = dh[0][ntl][1] + dh[1][ntl][1] + dl1[0][ntl][1] + dl1[1][ntl][1] + dl2[ntl][1];
                    ps0 = fmaf(a, smem[SM_RIGHT + j0 * 2 + sl0], ps0);
                    ps0 = fmaf(b, smem[SM_RIGHT + (j0 + 1) * 2 + sl0], ps0);
                }
                if (sel1 == h) {
                    float a = dh[0][ntl][2] + dh[1][ntl][2] + dl1[0][ntl][2] + dl1[1][ntl][2] + dl2[ntl][2];
                    float b = dh[0][ntl][3] + dh[1][ntl][3] + dl1[0][ntl][3] + dl1[1][ntl][3] + dl2[ntl][3];
                    ps1 = fmaf(a, smem[SM_RIGHT + j0 * 2 + sl1], ps1);
                    ps1 = fmaf(b, smem[SM_RIGHT + (j0 + 1) * 2 + sl1], ps1);
                }
            }
        }
    }

    ps0 += __shfl_xor_sync(0xffffffffu, ps0, 1);
    ps0 += __shfl_xor_sync(0xffffffffu, ps0, 2);
    ps1 += __shfl_xor_sync(0xffffffffu, ps1, 1);
    ps1 += __shfl_xor_sync(0xffffffffu, ps1, 2);
    __syncthreads();
    if (tq == 0) {
        smem[SM_RED + ng * 64 + r0] = ps0;
        smem[SM_RED + ng * 64 + r1] = ps1;
    }
    __syncthreads();
    if (tid < 64) {
        float psi = smem[SM_RED + tid] + smem[SM_RED + 64 + tid]
                  + smem[SM_RED + 128 + tid] + smem[SM_RED + 192 + tid];
        smem[SM_RED + tid] = logf(fmaxf(psi * psi, 1e-12f));
    }
    __syncthreads();
    if (tid == 0) {
        float s = 0.0f;
#pragma unroll 8
        for (int i = 0; i < 64; i++) s += smem[SM_RED + i];
        g_blocksums[bi] = s;
        __threadfence();
        unsigned o = atomicAdd(&g_fin, 1u);
        if (o == PSI_BLOCKS) {
            float tot = 0.0f;
            for (int i = 0; i < PSI_BLOCKS; i++) tot += __ldcg(&g_blocksums[i]);
            out[0] = g_logz - tot * (1.0f / (float)NBATCH);
            __threadfence();
            g_fin = 0;
            __threadfence();
        }
    }
}

extern "C" void kernel_launch(void* const* d_in, const int* in_sizes, int n_in,
                              void* d_out, int out_size) {
    const int*   cfg   = (const int*)d_in[0];
    const float* left  = (const float*)d_in[1];
    const float* bulk  = (const float*)d_in[2];
    const float* right = (const float*)d_in[3];

    cudaFuncSetAttribute(main_kernel, cudaFuncAttributeMaxDynamicSharedMemorySize,
                         SM_TOTALF * 4);

    pre_kernel<<<NBULK, 256>>>(bulk);
    main_kernel<<<TOTAL_BLOCKS, NTHREADS, SM_TOTALF * 4>>>(cfg, left, bulk, right,
                                                           (float*)d_out);
}

// round 13
// speedup vs baseline: 1.2633x; 1.2633x over previous
#include <cuda_runtime.h>
#include <cuda_bf16.h>
#include <math.h>
#include <stdint.h>
#include <cstdint>

#define NBULK        62
#define DDIM         64
#define NBATCH       8192
#define PSI_BLOCKS   128
#define TOTAL_BLOCKS (1 + PSI_BLOCKS)
#define NTHREADS     512
#define MBLK         64

// ---------------- psi-block shared memory layout (float offsets) -------------
#define ENV_STRIDE 68
#define SM_ENV     0                        // 64*68 = 4352 (env[m][k])
#define SM_RIGHT   4352                     // 128
#define SM_RED     4480                     // 256
#define SM_CFG     4736                     // 1024 floats (cfgS[site][m])
#define SM_B       5760                     // 2 x 8192 u32 (bf16 frags hi|lo), 64 KB
#define PSI_TOTALF (5760 + 16384)           // 22144 floats

// ---------------- logz-block shared memory layout ----------------------------
#define LZ_ENV   0                          // 64*68 = 4352
#define LZ_TMP   4352                       // 128*68 = 8704 (tmpT[(p,j)][d])
#define LZ_B1    13056                      // 8192 u32 (phase1 B frags hi|lo)
#define LZ_B2    21248                      // 8192 u32 (phase2 B frags hi|lo)
#define LZ_RED   29440                      // 256
#define LZ_TOTALF 29696

#define SM_TOTALF LZ_TOTALF                 // 118784 bytes

// ---------------- global scratch (zero-initialized at load) ------------------
__device__ float    g_bulkT [(size_t)NBULK * 8192];   // bf16 B frags hi|lo (psi + logz ph1)
__device__ float    g_bulkT2[(size_t)NBULK * 8192];   // bf16 B frags hi|lo (logz ph2)
__device__ float    g_blocksums[PSI_BLOCKS];
__device__ float    g_logz;
__device__ unsigned g_fin;

__device__ __forceinline__ void cp16(unsigned dst, const void* src) {
    asm volatile("cp.async.cg.shared.global [%0], [%1], 16;" :: "r"(dst), "l"(src) : "memory");
}
__device__ __forceinline__ void cp_commit() { asm volatile("cp.async.commit_group;" ::: "memory"); }
__device__ __forceinline__ void cp_wait0()  { asm volatile("cp.async.wait_group 0;" ::: "memory"); }

// m16n8k16 bf16 MMA, f32 accumulate in-place (native HMMA path)
__device__ __forceinline__ void mma16(float* d, const unsigned* a, unsigned b0, unsigned b1) {
    asm volatile("mma.sync.aligned.m16n8k16.row.col.f32.bf16.bf16.f32 "
                 "{%0,%1,%2,%3}, {%4,%5,%6,%7}, {%8,%9}, {%0,%1,%2,%3};"
                 : "+f"(d[0]), "+f"(d[1]), "+f"(d[2]), "+f"(d[3])
                 : "r"(a[0]), "r"(a[1]), "r"(a[2]), "r"(a[3]), "r"(b0), "r"(b1));
}

// split (x,y) into bf16x2 hi and bf16x2 lo (lo = rn(x - hi))
__device__ __forceinline__ void split2(float x, float y, unsigned& hi, unsigned& lo) {
    __nv_bfloat162 h = __floats2bfloat162_rn(x, y);   // .x = x (low half)
    hi = *reinterpret_cast<unsigned*>(&h);
    float rx = x - __bfloat162float(h.x);
    float ry = y - __bfloat162float(h.y);
    __nv_bfloat162 l = __floats2bfloat162_rn(rx, ry);
    lo = *reinterpret_cast<unsigned*>(&l);
}

// ============ pre-pass: bake bf16 hi/lo fragment-order operands ==============
__global__ void pre_kernel(const float* __restrict__ bulk) {
    const int t = blockIdx.x;
    const float* src = bulk + (size_t)t * 8192;       // [d][n], n = p*64+j
    unsigned short* d1 = (unsigned short*)(g_bulkT  + (size_t)t * 8192);
    unsigned short* d2 = (unsigned short*)(g_bulkT2 + (size_t)t * 8192);
    // B1 (psi + logz phase1): B[k][n] = src[k*128+n]; K=64 (4 kt16), N=128 (16 nt)
    for (int idx = threadIdx.x; idx < 8192; idx += blockDim.x) {
        int k = idx >> 7, n = idx & 127;
        float v = src[idx];
        __nv_bfloat16 hb = __float2bfloat16_rn(v);
        __nv_bfloat16 lb = __float2bfloat16_rn(v - __bfloat162float(hb));
        int kt   = k >> 4;
        int lane = ((n & 7) << 2) | ((k >> 1) & 3);
        int b    = (k >> 3) & 1;
        int h2   = k & 1;
        int u32i = ((kt * 16 + (n >> 3)) * 32 + lane) * 2 + b;    // 0..4095
        d1[u32i * 2 + h2]        = *reinterpret_cast<unsigned short*>(&hb);
        d1[8192 + u32i * 2 + h2] = *reinterpret_cast<unsigned short*>(&lb);
    }
    // B2 (logz phase2): B2[K][i] = src[(K&63)*128 + (K>>6)*64 + i]; K=128 (8 kt16), N=64 (8 nt)
    for (int idx = threadIdx.x; idx < 8192; idx += blockDim.x) {
        int K = idx >> 6, n = idx & 63;
        float v = src[(K & 63) * 128 + (K >> 6) * 64 + n];
        __nv_bfloat16 hb = __float2bfloat16_rn(v);
        __nv_bfloat16 lb = __float2bfloat16_rn(v - __bfloat162float(hb));
        int kt   = K >> 4;
        int lane = ((n & 7) << 2) | ((K >> 1) & 3);
        int b    = (K >> 3) & 1;
        int h2   = K & 1;
        int u32i = ((kt * 8 + (n >> 3)) * 32 + lane) * 2 + b;     // 0..4095
        d2[u32i * 2 + h2]        = *reinterpret_cast<unsigned short*>(&hb);
        d2[8192 + u32i * 2 + h2] = *reinterpret_cast<unsigned short*>(&lb);
    }
}

__global__ __launch_bounds__(NTHREADS, 1)
void main_kernel(const int* __restrict__ cfg,
                 const float* __restrict__ left,
                 const float* __restrict__ bulk,
                 const float* __restrict__ right,
                 float* __restrict__ out) {
    extern __shared__ float smem[];
    const int tid = threadIdx.x;
    const int lane = tid & 31;
    const int w = tid >> 5;
    const int g = lane >> 2, tq = lane & 3;
    const unsigned smem_base = (unsigned)__cvta_generic_to_shared(smem);

    if (blockIdx.x == 0) {
        // ========== log-Z: ONE block, bf16 tensor cores ==========
        unsigned* maxw = (unsigned*)(smem + LZ_RED);
        const unsigned b1_addr = smem_base + LZ_B1 * 4;
        const unsigned b2_addr = smem_base + LZ_B2 * 4;

        for (int idx = tid; idx < 4096; idx += NTHREADS) {
            int i = idx >> 6, j = idx & 63;
            smem[LZ_ENV + i * ENV_STRIDE + j] =
                left[i] * left[j] + left[64 + i] * left[64 + j];
        }
        {
            const float4* s1 = (const float4*)g_bulkT;
            const float4* s2 = (const float4*)g_bulkT2;
#pragma unroll
            for (int i = 0; i < 4; i++)
                cp16(b1_addr + (unsigned)(tid + (i << 9)) * 16u, s1 + tid + (i << 9));
#pragma unroll
            for (int i = 0; i < 4; i++)
                cp16(b2_addr + (unsigned)(tid + (i << 9)) * 16u, s2 + tid + (i << 9));
            cp_commit();
        }

        const int mt = w & 3;
        const int ng = w >> 2;          // 0..3
        const int r0 = mt * 16 + g, r1 = r0 + 8;
        float log_scale = 0.0f;

        for (int t = 0; t < NBULK; t++) {
            cp_wait0();
            __syncthreads();

            // ---- phase1: tmp = env @ [A0|A1]; store TRANSPOSED tmpT[n][d] ----
            {
                unsigned ah[4][4], al[4][4];
#pragma unroll
                for (int kt = 0; kt < 4; kt++) {
                    const int c0 = kt * 16 + 2 * tq;
                    float2 x0 = *(float2*)&smem[LZ_ENV + r0 * ENV_STRIDE + c0];
                    float2 x1 = *(float2*)&smem[LZ_ENV + r1 * ENV_STRIDE + c0];
                    float2 x2 = *(float2*)&smem[LZ_ENV + r0 * ENV_STRIDE + c0 + 8];
                    float2 x3 = *(float2*)&smem[LZ_ENV + r1 * ENV_STRIDE + c0 + 8];
                    split2(x0.x, x0.y, ah[kt][0], al[kt][0]);
                    split2(x1.x, x1.y, ah[kt][1], al[kt][1]);
                    split2(x2.x, x2.y, ah[kt][2], al[kt][2]);
                    split2(x3.x, x3.y, ah[kt][3], al[kt][3]);
                }
                const uint2* Bh = (const uint2*)((const unsigned*)(smem + LZ_B1));
                const uint2* Bl = Bh + 2048;
                float dh[4][4], dl1[4][4], dl2[4][4];
#pragma unroll
                for (int i = 0; i < 4; i++)
#pragma unroll
                    for (int j = 0; j < 4; j++) { dh[i][j] = 0.f; dl1[i][j] = 0.f; dl2[i][j] = 0.f; }
#pragma unroll
                for (int kt = 0; kt < 4; kt++)
#pragma unroll
                    for (int ntl = 0; ntl < 4; ntl++) {
                        uint2 bh = Bh[(kt * 16 + ng * 4 + ntl) * 32 + lane];
                        uint2 bl = Bl[(kt * 16 + ng * 4 + ntl) * 32 + lane];
                        mma16(dh[ntl],  ah[kt], bh.x, bh.y);
                        mma16(dl1[ntl], al[kt], bh.x, bh.y);
                        mma16(dl2[ntl], ah[kt], bl.x, bl.y);
                    }
#pragma unroll
                for (int ntl = 0; ntl < 4; ntl++) {
                    const int n0 = (ng * 4 + ntl) * 8 + 2 * tq;
                    smem[LZ_TMP + (n0    ) * ENV_STRIDE + r0] = dh[ntl][0] + dl1[ntl][0] + dl2[ntl][0];
                    smem[LZ_TMP + (n0 + 1) * ENV_STRIDE + r0] = dh[ntl][1] + dl1[ntl][1] + dl2[ntl][1];
                    smem[LZ_TMP + (n0    ) * ENV_STRIDE + r1] = dh[ntl][2] + dl1[ntl][2] + dl2[ntl][2];
                    smem[LZ_TMP + (n0 + 1) * ENV_STRIDE + r1] = dh[ntl][3] + dl1[ntl][3] + dl2[ntl][3];
                }
            }
            if (tid == 0) *maxw = 0u;
            __syncthreads();

            if (t + 1 < NBULK) {
                const float4* s1 = (const float4*)(g_bulkT + (size_t)(t + 1) * 8192);
#pragma unroll
                for (int i = 0; i < 4; i++)
                    cp16(b1_addr + (unsigned)(tid + (i << 9)) * 16u, s1 + tid + (i << 9));
                cp_commit();
            }

            // ---- phase2: env'[j][i] = sum_K tmpT[(p,j)][d] * B2[K][i] ----
            float ds[2][4];
            {
                float dh[2][4], dl1[2][4], dl2[2][4];
#pragma unroll
                for (int i = 0; i < 2; i++)
#pragma unroll
                    for (int j = 0; j < 4; j++) { dh[i][j] = 0.f; dl1[i][j] = 0.f; dl2[i][j] = 0.f; }
                const uint2* B2h = (const uint2*)((const unsigned*)(smem + LZ_B2));
                const uint2* B2l = B2h + 2048;
#pragma unroll
                for (int kt2 = 0; kt2 < 8; kt2++) {
                    const int p  = kt2 >> 2;
                    const int d0 = (kt2 & 3) * 16 + 2 * tq;
                    float2 x0 = *(float2*)&smem[LZ_TMP + (p * 64 + r0) * ENV_STRIDE + d0];
                    float2 x1 = *(float2*)&smem[LZ_TMP + (p * 64 + r1) * ENV_STRIDE + d0];
                    float2 x2 = *(float2*)&smem[LZ_TMP + (p * 64 + r0) * ENV_STRIDE + d0 + 8];
                    float2 x3 = *(float2*)&smem[LZ_TMP + (p * 64 + r1) * ENV_STRIDE + d0 + 8];
                    unsigned ah[4], al[4];
                    split2(x0.x, x0.y, ah[0], al[0]);
                    split2(x1.x, x1.y, ah[1], al[1]);
                    split2(x2.x, x2.y, ah[2], al[2]);
                    split2(x3.x, x3.y, ah[3], al[3]);
#pragma unroll
                    for (int ntl = 0; ntl < 2; ntl++) {
                        uint2 bh = B2h[(kt2 * 8 + ng * 2 + ntl) * 32 + lane];
                        uint2 bl = B2l[(kt2 * 8 + ng * 2 + ntl) * 32 + lane];
                        mma16(dh[ntl],  ah, bh.x, bh.y);
                        mma16(dl1[ntl], al, bh.x, bh.y);
                        mma16(dl2[ntl], ah, bl.x, bl.y);
                    }
                }
                float am = 0.0f;
#pragma unroll
                for (int ntl = 0; ntl < 2; ntl++)
#pragma unroll
                    for (int j = 0; j < 4; j++) {
                        ds[ntl][j] = dh[ntl][j] + dl1[ntl][j] + dl2[ntl][j];
                        am = fmaxf(am, fabsf(ds[ntl][j]));
                    }
#pragma unroll
                for (int off = 16; off > 0; off >>= 1)
                    am = fmaxf(am, __shfl_xor_sync(0xffffffffu, am, off));
                if (lane == 0) atomicMax(maxw, __float_as_uint(am));
            }
            __syncthreads();

            if (t + 1 < NBULK) {
                const float4* s2 = (const float4*)(g_bulkT2 + (size_t)(t + 1) * 8192);
#pragma unroll
                for (int i = 0; i < 4; i++)
                    cp16(b2_addr + (unsigned)(tid + (i << 9)) * 16u, s2 + tid + (i << 9));
                cp_commit();
            }

            const float scale = fmaxf(__uint_as_float(*maxw), 1e-30f);
            log_scale += logf(scale);
            const float inv = 1.0f / scale;
#pragma unroll
            for (int ntl = 0; ntl < 2; ntl++) {
                const int i0 = (ng * 2 + ntl) * 8 + 2 * tq;
                *(float2*)&smem[LZ_ENV + r0 * ENV_STRIDE + i0] =
                    make_float2(ds[ntl][0] * inv, ds[ntl][1] * inv);
                *(float2*)&smem[LZ_ENV + r1 * ENV_STRIDE + i0] =
                    make_float2(ds[ntl][2] * inv, ds[ntl][3] * inv);
            }
        }
        __syncthreads();

        float part = 0.0f;
        if (tid < 128) {
            int k = tid & 63, pp = tid >> 6;
            float s = 0.0f;
#pragma unroll 8
            for (int e = 0; e < 64; e++)
                s = fmaf(smem[LZ_ENV + k * ENV_STRIDE + e], right[e * 2 + pp], s);
            part = right[k * 2 + pp] * s;
        }
        if (tid < 128) smem[LZ_RED + 32 + tid] = part;
        __syncthreads();
        if (tid == 0) {
            float z = 0.0f;
            for (int i = 0; i < 128; i++) z += smem[LZ_RED + 32 + i];
            g_logz = logf(fmaxf(z, 1e-30f)) + log_scale;
            __threadfence();
            unsigned o = atomicAdd(&g_fin, 1u);
            if (o == PSI_BLOCKS) {
                float s = 0.0f;
                for (int i = 0; i < PSI_BLOCKS; i++) s += __ldcg(&g_blocksums[i]);
                out[0] = g_logz - s * (1.0f / (float)NBATCH);
                __threadfence();
                g_fin = 0;
                __threadfence();
            }
        }
        return;
    }

    // ======= psi: 128 blocks x 64 samples, bf16 mma.sync m16n8k16 =============
    const int bi = blockIdx.x - 1;
    const int m0 = bi * MBLK;
    const int mt = w & 3;
    const int ng = w >> 2;
    const int h = ng >> 1;
    const int r0 = mt * 16 + g, r1 = r0 + 8;
    unsigned char* cfgS = (unsigned char*)(smem + SM_CFG);
    const unsigned smemB_base = smem_base + SM_B * 4;

    {
        const float4* src = (const float4*)g_bulkT;
#pragma unroll
        for (int i = 0; i < 4; i++)
            cp16(smemB_base + (unsigned)(tid + (i << 9)) * 16u, src + tid + (i << 9));
        cp_commit();
    }

    for (int idx = tid; idx < 64 * MBLK; idx += NTHREADS) {
        int mm = idx >> 6, s = idx & 63;
        cfgS[s * MBLK + mm] = (unsigned char)cfg[(size_t)(m0 + mm) * 64 + s];
    }
    if (tid < 128) smem[SM_RIGHT + tid] = right[tid];
    __syncthreads();

    for (int idx = tid; idx < 64 * 64; idx += NTHREADS) {
        int k = idx >> 6, mm = idx & 63;
        smem[SM_ENV + mm * ENV_STRIDE + k] = left[(int)cfgS[mm] * 64 + k];
    }

    float ps0 = 0.0f, ps1 = 0.0f;

    for (int t = 0; t < NBULK; t++) {
        cp_wait0();
        __syncthreads();

        if (t + 1 < NBULK) {
            const float4* src = (const float4*)(g_bulkT + (size_t)(t + 1) * 8192);
            unsigned dst = smemB_base + (unsigned)(((t + 1) & 1) * 32768u);
#pragma unroll
            for (int i = 0; i < 4; i++)
                cp16(dst + (unsigned)(tid + (i << 9)) * 16u, src + tid + (i << 9));
            cp_commit();
        }

        // A frags: env rows r0/r1, bf16 hi/lo split
        unsigned ah[4][4], al[4][4];
#pragma unroll
        for (int kt = 0; kt < 4; kt++) {
            const int c0 = kt * 16 + 2 * tq;
            float2 x0 = *(float2*)&smem[SM_ENV + r0 * ENV_STRIDE + c0];
            float2 x1 = *(float2*)&smem[SM_ENV + r1 * ENV_STRIDE + c0];
            float2 x2 = *(float2*)&smem[SM_ENV + r0 * ENV_STRIDE + c0 + 8];
            float2 x3 = *(float2*)&smem[SM_ENV + r1 * ENV_STRIDE + c0 + 8];
            split2(x0.x, x0.y, ah[kt][0], al[kt][0]);
            split2(x1.x, x1.y, ah[kt][1], al[kt][1]);
            split2(x2.x, x2.y, ah[kt][2], al[kt][2]);
            split2(x3.x, x3.y, ah[kt][3], al[kt][3]);
        }

        const uint2* Bh = (const uint2*)((const unsigned*)(smem + SM_B) + (t & 1) * 8192);
        const uint2* Bl = Bh + 2048;

        float dh[4][4], dl1[4][4], dl2[4][4];
#pragma unroll
        for (int i = 0; i < 4; i++)
#pragma unroll
            for (int j = 0; j < 4; j++) { dh[i][j] = 0.f; dl1[i][j] = 0.f; dl2[i][j] = 0.f; }

#pragma unroll
        for (int kt = 0; kt < 4; kt++)
#pragma unroll
            for (int ntl = 0; ntl < 4; ntl++) {
                uint2 bh = Bh[(kt * 16 + ng * 4 + ntl) * 32 + lane];
                uint2 bl = Bl[(kt * 16 + ng * 4 + ntl) * 32 + lane];
                mma16(dh[ntl],  ah[kt], bh.x, bh.y);
                mma16(dl1[ntl], al[kt], bh.x, bh.y);
                mma16(dl2[ntl], ah[kt], bl.x, bl.y);
            }
        __syncthreads();   // env + B[t] reads done

        if (t < NBULK - 1) {
            const int sel0 = cfgS[(t + 1) * MBLK + r0];
            const int sel1 = cfgS[(t + 1) * MBLK + r1];
#pragma unroll
            for (int ntl = 0; ntl < 4; ntl++) {
                const int j0 = (ng & 1) * 32 + ntl * 8 + 2 * tq;
                if (sel0 == h)
                    *(float2*)&smem[SM_ENV + r0 * ENV_STRIDE + j0] =
                        make_float2(dh[ntl][0] + dl1[ntl][0] + dl2[ntl][0],
                                    dh[ntl][1] + dl1[ntl][1] + dl2[ntl][1]);
                if (sel1 == h)
                    *(float2*)&smem[SM_ENV + r1 * ENV_STRIDE + j0] =
                        make_float2(dh[ntl][2] + dl1[ntl][2] + dl2[ntl][2],
                                    dh[ntl][3] + dl1[ntl][3] + dl2[ntl][3]);
            }
        } else {
            const int sel0 = cfgS[62 * MBLK + r0], sl0 = cfgS[63 * MBLK + r0];
            const int sel1 = cfgS[62 * MBLK + r1], sl1 = cfgS[63 * MBLK + r1];
#pragma unroll
            for (int ntl = 0; ntl < 4; ntl++) {
                const int j0 = (ng & 1) * 32 + ntl * 8 + 2 * tq;
                if (sel0 == h) {
                    float a = dh[ntl][0] + dl1[ntl][0] + dl2[ntl][0];
                    float b = dh[ntl][1] + dl1[ntl][1] + dl2[ntl][1];
                    ps0 = fmaf(a, smem[SM_RIGHT + j0 * 2 + sl0], ps0);
                    ps0 = fmaf(b, smem[SM_RIGHT + (j0 + 1) * 2 + sl0], ps0);
                }
                if (sel1 == h) {
                    float a = dh[ntl][2] + dl1[ntl][2] + dl2[ntl][2];
                    float b = dh[ntl][3] + dl1[ntl][3] + dl2[ntl][3];
                    ps1 = fmaf(a, smem[SM_RIGHT + j0 * 2 + sl1], ps1);
                    ps1 = fmaf(b, smem[SM_RIGHT + (j0 + 1) * 2 + sl1], ps1);
                }
            }
        }
    }

    ps0 += __shfl_xor_sync(0xffffffffu, ps0, 1);
    ps0 += __shfl_xor_sync(0xffffffffu, ps0, 2);
    ps1 += __shfl_xor_sync(0xffffffffu, ps1, 1);
    ps1 += __shfl_xor_sync(0xffffffffu, ps1, 2);
    __syncthreads();
    if (tq == 0) {
        smem[SM_RED + ng * 64 + r0] = ps0;
        smem[SM_RED + ng * 64 + r1] = ps1;
    }
    __syncthreads();
    if (tid < 64) {
        float psi = smem[SM_RED + tid] + smem[SM_RED + 64 + tid]
                  + smem[SM_RED + 128 + tid] + smem[SM_RED + 192 + tid];
        smem[SM_RED + tid] = logf(fmaxf(psi * psi, 1e-12f));
    }
    __syncthreads();
    if (tid == 0) {
        float s = 0.0f;
#pragma unroll 8
        for (int i = 0; i < 64; i++) s += smem[SM_RED + i];
        g_blocksums[bi] = s;
        __threadfence();
        unsigned o = atomicAdd(&g_fin, 1u);
        if (o == PSI_BLOCKS) {
            float tot = 0.0f;
            for (int i = 0; i < PSI_BLOCKS; i++) tot += __ldcg(&g_blocksums[i]);
            out[0] = g_logz - tot * (1.0f / (float)NBATCH);
            __threadfence();
            g_fin = 0;
            __threadfence();
        }
    }
}

extern "C" void kernel_launch(void* const* d_in, const int* in_sizes, int n_in,
                              void* d_out, int out_size) {
    const int*   cfg   = (const int*)d_in[0];
    const float* left  = (const float*)d_in[1];
    const float* bulk  = (const float*)d_in[2];
    const float* right = (const float*)d_in[3];

    cudaFuncSetAttribute(main_kernel, cudaFuncAttributeMaxDynamicSharedMemorySize,
                         SM_TOTALF * 4);

    pre_kernel<<<NBULK, 256>>>(bulk);
    main_kernel<<<TOTAL_BLOCKS, NTHREADS, SM_TOTALF * 4>>>(cfg, left, bulk, right,
                                                           (float*)d_out);
}

// round 14
// speedup vs baseline: 1.2769x; 1.0108x over previous
#include <cuda_runtime.h>
#include <cuda_bf16.h>
#include <math.h>
#include <stdint.h>
#include <cstdint>

#define NBULK        62
#define DDIM         64
#define NBATCH       8192
#define PSI_BLOCKS   128
#define TOTAL_BLOCKS (1 + PSI_BLOCKS)
#define NTHREADS     512
#define MBLK         64

// ---------------- psi-block shared memory layout (float/word offsets) --------
#define EW         36                       // env row stride in u32 words
#define SM_EHI     0                        // 64*36 = 2304 words (bf16x2 hi)
#define SM_ELO     2304                     // 2304 words (bf16x2 lo)
#define SM_RIGHT   4608                     // 128 floats
#define SM_RED     4736                     // 256
#define SM_CFG     4992                     // 1024 floats (cfgS[site][m])
#define SM_B       6016                     // byte 24064 (128B aligned); 2 x 8192 u32
#define PSI_TOTALF (6016 + 16384)

// ---------------- logz-block shared memory layout (unchanged from R12) -------
#define ENV_STRIDE 68
#define LZ_ENV   0                          // 64*68 = 4352
#define LZ_TMP   4352                       // 128*68 = 8704 (tmpT[(p,j)][d])
#define LZ_B1    13056                      // 8192 u32
#define LZ_B2    21248                      // 8192 u32
#define LZ_RED   29440                      // 256
#define LZ_TOTALF 29696

#define SM_TOTALF LZ_TOTALF                 // 118784 bytes

// ---------------- global scratch (zero-initialized at load) ------------------
__device__ float    g_bulkT [(size_t)NBULK * 8192];   // bf16 B frags hi|lo (psi + logz ph1)
__device__ float    g_bulkT2[(size_t)NBULK * 8192];   // bf16 B frags hi|lo (logz ph2)
__device__ float    g_blocksums[PSI_BLOCKS];
__device__ float    g_logz;
__device__ unsigned g_fin;

__device__ __forceinline__ void cp16(unsigned dst, const void* src) {
    asm volatile("cp.async.cg.shared.global [%0], [%1], 16;" :: "r"(dst), "l"(src) : "memory");
}
__device__ __forceinline__ void cp_commit() { asm volatile("cp.async.commit_group;" ::: "memory"); }
__device__ __forceinline__ void cp_wait0()  { asm volatile("cp.async.wait_group 0;" ::: "memory"); }
__device__ __forceinline__ void barn(int id) {
    asm volatile("bar.sync %0, 128;" :: "r"(id) : "memory");
}

// m16n8k16 bf16 MMA, f32 accumulate in-place
__device__ __forceinline__ void mma16(float* d, const unsigned* a, unsigned b0, unsigned b1) {
    asm volatile("mma.sync.aligned.m16n8k16.row.col.f32.bf16.bf16.f32 "
                 "{%0,%1,%2,%3}, {%4,%5,%6,%7}, {%8,%9}, {%0,%1,%2,%3};"
                 : "+f"(d[0]), "+f"(d[1]), "+f"(d[2]), "+f"(d[3])
                 : "r"(a[0]), "r"(a[1]), "r"(a[2]), "r"(a[3]), "r"(b0), "r"(b1));
}

// split (x,y) into bf16x2 hi and bf16x2 lo
__device__ __forceinline__ void split2(float x, float y, unsigned& hi, unsigned& lo) {
    __nv_bfloat162 h = __floats2bfloat162_rn(x, y);
    hi = *reinterpret_cast<unsigned*>(&h);
    float rx = x - __bfloat162float(h.x);
    float ry = y - __bfloat162float(h.y);
    __nv_bfloat162 l = __floats2bfloat162_rn(rx, ry);
    lo = *reinterpret_cast<unsigned*>(&l);
}

// ============ pre-pass: bake bf16 hi/lo fragment-order operands ==============
__global__ void pre_kernel(const float* __restrict__ bulk) {
    const int t = blockIdx.x;
    const float* src = bulk + (size_t)t * 8192;       // [d][n], n = p*64+j
    unsigned short* d1 = (unsigned short*)(g_bulkT  + (size_t)t * 8192);
    unsigned short* d2 = (unsigned short*)(g_bulkT2 + (size_t)t * 8192);
    for (int idx = threadIdx.x; idx < 8192; idx += blockDim.x) {
        int k = idx >> 7, n = idx & 127;
        float v = src[idx];
        __nv_bfloat16 hb = __float2bfloat16_rn(v);
        __nv_bfloat16 lb = __float2bfloat16_rn(v - __bfloat162float(hb));
        int kt   = k >> 4;
        int lane = ((n & 7) << 2) | ((k >> 1) & 3);
        int b    = (k >> 3) & 1;
        int h2   = k & 1;
        int u32i = ((kt * 16 + (n >> 3)) * 32 + lane) * 2 + b;
        d1[u32i * 2 + h2]        = *reinterpret_cast<unsigned short*>(&hb);
        d1[8192 + u32i * 2 + h2] = *reinterpret_cast<unsigned short*>(&lb);
    }
    for (int idx = threadIdx.x; idx < 8192; idx += blockDim.x) {
        int K = idx >> 6, n = idx & 63;
        float v = src[(K & 63) * 128 + (K >> 6) * 64 + n];
        __nv_bfloat16 hb = __float2bfloat16_rn(v);
        __nv_bfloat16 lb = __float2bfloat16_rn(v - __bfloat162float(hb));
        int kt   = K >> 4;
        int lane = ((n & 7) << 2) | ((K >> 1) & 3);
        int b    = (K >> 3) & 1;
        int h2   = K & 1;
        int u32i = ((kt * 8 + (n >> 3)) * 32 + lane) * 2 + b;
        d2[u32i * 2 + h2]        = *reinterpret_cast<unsigned short*>(&hb);
        d2[8192 + u32i * 2 + h2] = *reinterpret_cast<unsigned short*>(&lb);
    }
}

__global__ __launch_bounds__(NTHREADS, 1)
void main_kernel(const int* __restrict__ cfg,
                 const float* __restrict__ left,
                 const float* __restrict__ bulk,
                 const float* __restrict__ right,
                 float* __restrict__ out) {
    extern __shared__ float smem[];
    const int tid = threadIdx.x;
    const int lane = tid & 31;
    const int w = tid >> 5;
    const int g = lane >> 2, tq = lane & 3;
    const unsigned smem_base = (unsigned)__cvta_generic_to_shared(smem);

    if (blockIdx.x == 0) {
        // ========== log-Z: ONE block, bf16 tensor cores (unchanged R12) ==========
        unsigned* maxw = (unsigned*)(smem + LZ_RED);
        const unsigned b1_addr = smem_base + LZ_B1 * 4;
        const unsigned b2_addr = smem_base + LZ_B2 * 4;

        for (int idx = tid; idx < 4096; idx += NTHREADS) {
            int i = idx >> 6, j = idx & 63;
            smem[LZ_ENV + i * ENV_STRIDE + j] =
                left[i] * left[j] + left[64 + i] * left[64 + j];
        }
        {
            const float4* s1 = (const float4*)g_bulkT;
            const float4* s2 = (const float4*)g_bulkT2;
#pragma unroll
            for (int i = 0; i < 4; i++)
                cp16(b1_addr + (unsigned)(tid + (i << 9)) * 16u, s1 + tid + (i << 9));
#pragma unroll
            for (int i = 0; i < 4; i++)
                cp16(b2_addr + (unsigned)(tid + (i << 9)) * 16u, s2 + tid + (i << 9));
            cp_commit();
        }

        const int mt = w & 3;
        const int ng = w >> 2;
        const int r0 = mt * 16 + g, r1 = r0 + 8;
        float log_scale = 0.0f;

        for (int t = 0; t < NBULK; t++) {
            cp_wait0();
            __syncthreads();

            {
                unsigned ah[4][4], al[4][4];
#pragma unroll
                for (int kt = 0; kt < 4; kt++) {
                    const int c0 = kt * 16 + 2 * tq;
                    float2 x0 = *(float2*)&smem[LZ_ENV + r0 * ENV_STRIDE + c0];
                    float2 x1 = *(float2*)&smem[LZ_ENV + r1 * ENV_STRIDE + c0];
                    float2 x2 = *(float2*)&smem[LZ_ENV + r0 * ENV_STRIDE + c0 + 8];
                    float2 x3 = *(float2*)&smem[LZ_ENV + r1 * ENV_STRIDE + c0 + 8];
                    split2(x0.x, x0.y, ah[kt][0], al[kt][0]);
                    split2(x1.x, x1.y, ah[kt][1], al[kt][1]);
                    split2(x2.x, x2.y, ah[kt][2], al[kt][2]);
                    split2(x3.x, x3.y, ah[kt][3], al[kt][3]);
                }
                const uint2* Bh = (const uint2*)((const unsigned*)(smem + LZ_B1));
                const uint2* Bl = Bh + 2048;
                float dh[4][4], dl1[4][4], dl2[4][4];
#pragma unroll
                for (int i = 0; i < 4; i++)
#pragma unroll
                    for (int j = 0; j < 4; j++) { dh[i][j] = 0.f; dl1[i][j] = 0.f; dl2[i][j] = 0.f; }
#pragma unroll
                for (int kt = 0; kt < 4; kt++)
#pragma unroll
                    for (int ntl = 0; ntl < 4; ntl++) {
                        uint2 bh = Bh[(kt * 16 + ng * 4 + ntl) * 32 + lane];
                        uint2 bl = Bl[(kt * 16 + ng * 4 + ntl) * 32 + lane];
                        mma16(dh[ntl],  ah[kt], bh.x, bh.y);
                        mma16(dl1[ntl], al[kt], bh.x, bh.y);
                        mma16(dl2[ntl], ah[kt], bl.x, bl.y);
                    }
#pragma unroll
                for (int ntl = 0; ntl < 4; ntl++) {
                    const int n0 = (ng * 4 + ntl) * 8 + 2 * tq;
                    smem[LZ_TMP + (n0    ) * ENV_STRIDE + r0] = dh[ntl][0] + dl1[ntl][0] + dl2[ntl][0];
                    smem[LZ_TMP + (n0 + 1) * ENV_STRIDE + r0] = dh[ntl][1] + dl1[ntl][1] + dl2[ntl][1];
                    smem[LZ_TMP + (n0    ) * ENV_STRIDE + r1] = dh[ntl][2] + dl1[ntl][2] + dl2[ntl][2];
                    smem[LZ_TMP + (n0 + 1) * ENV_STRIDE + r1] = dh[ntl][3] + dl1[ntl][3] + dl2[ntl][3];
                }
            }
            if (tid == 0) *maxw = 0u;
            __syncthreads();

            if (t + 1 < NBULK) {
                const float4* s1 = (const float4*)(g_bulkT + (size_t)(t + 1) * 8192);
#pragma unroll
                for (int i = 0; i < 4; i++)
                    cp16(b1_addr + (unsigned)(tid + (i << 9)) * 16u, s1 + tid + (i << 9));
                cp_commit();
            }

            float ds[2][4];
            {
                float dh[2][4], dl1[2][4], dl2[2][4];
#pragma unroll
                for (int i = 0; i < 2; i++)
#pragma unroll
                    for (int j = 0; j < 4; j++) { dh[i][j] = 0.f; dl1[i][j] = 0.f; dl2[i][j] = 0.f; }
                const uint2* B2h = (const uint2*)((const unsigned*)(smem + LZ_B2));
                const uint2* B2l = B2h + 2048;
#pragma unroll
                for (int kt2 = 0; kt2 < 8; kt2++) {
                    const int p  = kt2 >> 2;
                    const int d0 = (kt2 & 3) * 16 + 2 * tq;
                    float2 x0 = *(float2*)&smem[LZ_TMP + (p * 64 + r0) * ENV_STRIDE + d0];
                    float2 x1 = *(float2*)&smem[LZ_TMP + (p * 64 + r1) * ENV_STRIDE + d0];
                    float2 x2 = *(float2*)&smem[LZ_TMP + (p * 64 + r0) * ENV_STRIDE + d0 + 8];
                    float2 x3 = *(float2*)&smem[LZ_TMP + (p * 64 + r1) * ENV_STRIDE + d0 + 8];
                    unsigned ah[4], al[4];
                    split2(x0.x, x0.y, ah[0], al[0]);
                    split2(x1.x, x1.y, ah[1], al[1]);
                    split2(x2.x, x2.y, ah[2], al[2]);
                    split2(x3.x, x3.y, ah[3], al[3]);
#pragma unroll
                    for (int ntl = 0; ntl < 2; ntl++) {
                        uint2 bh = B2h[(kt2 * 8 + ng * 2 + ntl) * 32 + lane];
                        uint2 bl = B2l[(kt2 * 8 + ng * 2 + ntl) * 32 + lane];
                        mma16(dh[ntl],  ah, bh.x, bh.y);
                        mma16(dl1[ntl], al, bh.x, bh.y);
                        mma16(dl2[ntl], ah, bl.x, bl.y);
                    }
                }
                float am = 0.0f;
#pragma unroll
                for (int ntl = 0; ntl < 2; ntl++)
#pragma unroll
                    for (int j = 0; j < 4; j++) {
                        ds[ntl][j] = dh[ntl][j] + dl1[ntl][j] + dl2[ntl][j];
                        am = fmaxf(am, fabsf(ds[ntl][j]));
                    }
#pragma unroll
                for (int off = 16; off > 0; off >>= 1)
                    am = fmaxf(am, __shfl_xor_sync(0xffffffffu, am, off));
                if (lane == 0) atomicMax(maxw, __float_as_uint(am));
            }
            __syncthreads();

            if (t + 1 < NBULK) {
                const float4* s2 = (const float4*)(g_bulkT2 + (size_t)(t + 1) * 8192);
#pragma unroll
                for (int i = 0; i < 4; i++)
                    cp16(b2_addr + (unsigned)(tid + (i << 9)) * 16u, s2 + tid + (i << 9));
                cp_commit();
            }

            const float scale = fmaxf(__uint_as_float(*maxw), 1e-30f);
            log_scale += logf(scale);
            const float inv = 1.0f / scale;
#pragma unroll
            for (int ntl = 0; ntl < 2; ntl++) {
                const int i0 = (ng * 2 + ntl) * 8 + 2 * tq;
                *(float2*)&smem[LZ_ENV + r0 * ENV_STRIDE + i0] =
                    make_float2(ds[ntl][0] * inv, ds[ntl][1] * inv);
                *(float2*)&smem[LZ_ENV + r1 * ENV_STRIDE + i0] =
                    make_float2(ds[ntl][2] * inv, ds[ntl][3] * inv);
            }
        }
        __syncthreads();

        float part = 0.0f;
        if (tid < 128) {
            int k = tid & 63, pp = tid >> 6;
            float s = 0.0f;
#pragma unroll 8
            for (int e = 0; e < 64; e++)
                s = fmaf(smem[LZ_ENV + k * ENV_STRIDE + e], right[e * 2 + pp], s);
            part = right[k * 2 + pp] * s;
        }
        if (tid < 128) smem[LZ_RED + 32 + tid] = part;
        __syncthreads();
        if (tid == 0) {
            float z = 0.0f;
            for (int i = 0; i < 128; i++) z += smem[LZ_RED + 32 + i];
            g_logz = logf(fmaxf(z, 1e-30f)) + log_scale;
            __threadfence();
            unsigned o = atomicAdd(&g_fin, 1u);
            if (o == PSI_BLOCKS) {
                float s = 0.0f;
                for (int i = 0; i < PSI_BLOCKS; i++) s += __ldcg(&g_blocksums[i]);
                out[0] = g_logz - s * (1.0f / (float)NBATCH);
                __threadfence();
                g_fin = 0;
                __threadfence();
            }
        }
        return;
    }

    // ======= psi: 128 blocks x 64 samples, bf16-resident env ==================
    const int bi = blockIdx.x - 1;
    const int m0 = bi * MBLK;
    const int mt = w & 3;
    const int ng = w >> 2;
    const int h = ng >> 1;
    const int r0 = mt * 16 + g, r1 = r0 + 8;
    unsigned char* cfgS = (unsigned char*)(smem + SM_CFG);
    unsigned* ehi = (unsigned*)(smem + SM_EHI);
    unsigned* elo = (unsigned*)(smem + SM_ELO);
    const unsigned smemB_base = smem_base + SM_B * 4;

    {
        const float4* src = (const float4*)g_bulkT;
#pragma unroll
        for (int i = 0; i < 4; i++)
            cp16(smemB_base + (unsigned)(tid + (i << 9)) * 16u, src + tid + (i << 9));
        cp_commit();
    }

    for (int idx = tid; idx < 64 * MBLK; idx += NTHREADS) {
        int mm = idx >> 6, s = idx & 63;
        cfgS[s * MBLK + mm] = (unsigned char)cfg[(size_t)(m0 + mm) * 64 + s];
    }
    if (tid < 128) smem[SM_RIGHT + tid] = right[tid];
    __syncthreads();

    // env0[m] = left[cfg0(m)], stored as hi/lo bf16x2 words
    for (int idx = tid; idx < 64 * 32; idx += NTHREADS) {
        int mm = idx >> 5, wd = idx & 31;
        const float* lr = left + (int)cfgS[mm] * 64 + 2 * wd;
        unsigned hi, lo;
        split2(lr[0], lr[1], hi, lo);
        ehi[mm * EW + wd] = hi;
        elo[mm * EW + wd] = lo;
    }
    __syncthreads();

    float ps0 = 0.0f, ps1 = 0.0f;

    for (int t = 0; t < NBULK; t++) {
        cp_wait0();
        __syncthreads();

        if (t + 1 < NBULK) {
            const float4* src = (const float4*)(g_bulkT + (size_t)(t + 1) * 8192);
            unsigned dst = smemB_base + (unsigned)(((t + 1) & 1) * 32768u);
#pragma unroll
            for (int i = 0; i < 4; i++)
                cp16(dst + (unsigned)(tid + (i << 9)) * 16u, src + tid + (i << 9));
            cp_commit();
        }

        // A frags: direct word loads, no conversion
        unsigned ah[4][4], al[4][4];
#pragma unroll
        for (int kt = 0; kt < 4; kt++) {
            const int b0i = r0 * EW + kt * 8 + tq;
            const int b1i = r1 * EW + kt * 8 + tq;
            ah[kt][0] = ehi[b0i];     ah[kt][1] = ehi[b1i];
            ah[kt][2] = ehi[b0i + 4]; ah[kt][3] = ehi[b1i + 4];
            al[kt][0] = elo[b0i];     al[kt][1] = elo[b1i];
            al[kt][2] = elo[b0i + 4]; al[kt][3] = elo[b1i + 4];
        }
        barn(mt + 1);   // all env reads of this mt group done -> epilogue may write

        const uint2* Bh = (const uint2*)((const unsigned*)(smem + SM_B) + (t & 1) * 8192);
        const uint2* Bl = Bh + 2048;

        float dh[4][4], dl1[4][4], dl2[4][4];
#pragma unroll
        for (int i = 0; i < 4; i++)
#pragma unroll
            for (int j = 0; j < 4; j++) { dh[i][j] = 0.f; dl1[i][j] = 0.f; dl2[i][j] = 0.f; }

#pragma unroll
        for (int kt = 0; kt < 4; kt++)
#pragma unroll
            for (int ntl = 0; ntl < 4; ntl++) {
                uint2 bh = Bh[(kt * 16 + ng * 4 + ntl) * 32 + lane];
                uint2 bl = Bl[(kt * 16 + ng * 4 + ntl) * 32 + lane];
                mma16(dh[ntl],  ah[kt], bh.x, bh.y);
                mma16(dl1[ntl], al[kt], bh.x, bh.y);
                mma16(dl2[ntl], ah[kt], bl.x, bl.y);
            }

        if (t < NBULK - 1) {
            const int sel0 = cfgS[(t + 1) * MBLK + r0];
            const int sel1 = cfgS[(t + 1) * MBLK + r1];
#pragma unroll
            for (int ntl = 0; ntl < 4; ntl++) {
                const int wd = (ng & 1) * 16 + ntl * 4 + tq;   // word index in row
                if (sel0 == h) {
                    unsigned hi, lo;
                    split2(dh[ntl][0] + dl1[ntl][0] + dl2[ntl][0],
                           dh[ntl][1] + dl1[ntl][1] + dl2[ntl][1], hi, lo);
                    ehi[r0 * EW + wd] = hi;
                    elo[r0 * EW + wd] = lo;
                }
                if (sel1 == h) {
                    unsigned hi, lo;
                    split2(dh[ntl][2] + dl1[ntl][2] + dl2[ntl][2],
                           dh[ntl][3] + dl1[ntl][3] + dl2[ntl][3], hi, lo);
                    ehi[r1 * EW + wd] = hi;
                    elo[r1 * EW + wd] = lo;
                }
            }
        } else {
            const int sel0 = cfgS[62 * MBLK + r0], sl0 = cfgS[63 * MBLK + r0];
            const int sel1 = cfgS[62 * MBLK + r1], sl1 = cfgS[63 * MBLK + r1];
#pragma unroll
            for (int ntl = 0; ntl < 4; ntl++) {
                const int j0 = (ng & 1) * 32 + ntl * 8 + 2 * tq;
                if (sel0 == h) {
                    float a = dh[ntl][0] + dl1[ntl][0] + dl2[ntl][0];
                    float b = dh[ntl][1] + dl1[ntl][1] + dl2[ntl][1];
                    ps0 = fmaf(a, smem[SM_RIGHT + j0 * 2 + sl0], ps0);
                    ps0 = fmaf(b, smem[SM_RIGHT + (j0 + 1) * 2 + sl0], ps0);
                }
                if (sel1 == h) {
                    float a = dh[ntl][2] + dl1[ntl][2] + dl2[ntl][2];
                    float b = dh[ntl][3] + dl1[ntl][3] + dl2[ntl][3];
                    ps1 = fmaf(a, smem[SM_RIGHT + j0 * 2 + sl1], ps1);
                    ps1 = fmaf(b, smem[SM_RIGHT + (j0 + 1) * 2 + sl1], ps1);
                }
            }
        }
    }

    ps0 += __shfl_xor_sync(0xffffffffu, ps0, 1);
    ps0 += __shfl_xor_sync(0xffffffffu, ps0, 2);
    ps1 += __shfl_xor_sync(0xffffffffu, ps1, 1);
    ps1 += __shfl_xor_sync(0xffffffffu, ps1, 2);
    __syncthreads();
    if (tq == 0) {
        smem[SM_RED + ng * 64 + r0] = ps0;
        smem[SM_RED + ng * 64 + r1] = ps1;
    }
    __syncthreads();
    if (tid < 64) {
        float psi = smem[SM_RED + tid] + smem[SM_RED + 64 + tid]
                  + smem[SM_RED + 128 + tid] + smem[SM_RED + 192 + tid];
        smem[SM_RED + tid] = logf(fmaxf(psi * psi, 1e-12f));
    }
    __syncthreads();
    if (tid == 0) {
        float s = 0.0f;
#pragma unroll 8
        for (int i = 0; i < 64; i++) s += smem[SM_RED + i];
        g_blocksums[bi] = s;
        __threadfence();
        unsigned o = atomicAdd(&g_fin, 1u);
        if (o == PSI_BLOCKS) {
            float tot = 0.0f;
            for (int i = 0; i < PSI_BLOCKS; i++) tot += __ldcg(&g_blocksums[i]);
            out[0] = g_logz - tot * (1.0f / (float)NBATCH);
            __threadfence();
            g_fin = 0;
            __threadfence();
        }
    }
}

extern "C" void kernel_launch(void* const* d_in, const int* in_sizes, int n_in,
                              void* d_out, int out_size) {
    const int*   cfg   = (const int*)d_in[0];
    const float* left  = (const float*)d_in[1];
    const float* bulk  = (const float*)d_in[2];
    const float* right = (const float*)d_in[3];

    cudaFuncSetAttribute(main_kernel, cudaFuncAttributeMaxDynamicSharedMemorySize,
                         SM_TOTALF * 4);

    pre_kernel<<<NBULK, 256>>>(bulk);
    main_kernel<<<TOTAL_BLOCKS, NTHREADS, SM_TOTALF * 4>>>(cfg, left, bulk, right,
                                                           (float*)d_out);
}